// round 11
// baseline (speedup 1.0000x reference)
#include <cuda_runtime.h>
#include <cuda_fp16.h>
#include <cstdint>

#define TDIM 8192
#define DDIM 4096

// ---- device scratch (allocation-free rule: __device__ globals) ----
static __device__ __half g_w1[(size_t)DDIM * DDIM];
static __device__ __half g_w2[(size_t)DDIM * DDIM];
static __device__ __half g_a[(size_t)TDIM * DDIM];
static __device__ __half g_h[(size_t)TDIM * DDIM];

// ---- dequant: int32 codes [D,D] * 2^scales [D,D/32] -> fp16 [D,D] (exact) ----
// E2M1 decode via PRMT: positive magnitudes {0,.5,1,1.5,2,3,4,6} have fp16
// high bytes {00,38,3C,3E,40,42,44,46}; low byte is 0. Sign = code bit 3.
__global__ void dequant_kernel(const int* __restrict__ codes,
                               const float* __restrict__ scales,
                               int which) {
    __half* __restrict__ out = which ? g_w2 : g_w1;
    size_t base = ((size_t)blockIdx.x * blockDim.x + threadIdx.x) * 8;
    const int4 c0 = *reinterpret_cast<const int4*>(codes + base);
    const int4 c1 = *reinterpret_cast<const int4*>(codes + base + 4);
    float s = __ldg(scales + (base >> 12) * (DDIM / 32) + ((base & 4095) >> 5));
    const __half2 hs2 = __half2half2(__float2half_rn(s));

    uint4 o;
    {
        uint32_t sel = (c0.x & 7) | ((c0.y & 7) << 4) | ((c0.z & 7) << 8) |
                       ((c0.w & 7) << 12);
        uint32_t hb = __byte_perm(0x3E3C3800u, 0x46444240u, sel);
        uint32_t p0 = __byte_perm(hb, 0, 0x1404) |
                      ((c0.x & 8) << 12) | ((c0.y & 8) << 28);
        uint32_t p1 = __byte_perm(hb, 0, 0x3424) |
                      ((c0.z & 8) << 12) | ((c0.w & 8) << 28);
        __half2 r0 = __hmul2(*reinterpret_cast<__half2*>(&p0), hs2);
        __half2 r1 = __hmul2(*reinterpret_cast<__half2*>(&p1), hs2);
        o.x = *reinterpret_cast<uint32_t*>(&r0);
        o.y = *reinterpret_cast<uint32_t*>(&r1);
    }
    {
        uint32_t sel = (c1.x & 7) | ((c1.y & 7) << 4) | ((c1.z & 7) << 8) |
                       ((c1.w & 7) << 12);
        uint32_t hb = __byte_perm(0x3E3C3800u, 0x46444240u, sel);
        uint32_t p0 = __byte_perm(hb, 0, 0x1404) |
                      ((c1.x & 8) << 12) | ((c1.y & 8) << 28);
        uint32_t p1 = __byte_perm(hb, 0, 0x3424) |
                      ((c1.z & 8) << 12) | ((c1.w & 8) << 28);
        __half2 r0 = __hmul2(*reinterpret_cast<__half2*>(&p0), hs2);
        __half2 r1 = __hmul2(*reinterpret_cast<__half2*>(&p1), hs2);
        o.z = *reinterpret_cast<uint32_t*>(&r0);
        o.w = *reinterpret_cast<uint32_t*>(&r1);
    }
    *reinterpret_cast<uint4*>(out + base) = o;
}

// ---- convert fp32 x -> fp16, 8 elems/thread ----
__global__ void split_kernel(const float* __restrict__ x) {
    size_t base = ((size_t)blockIdx.x * blockDim.x + threadIdx.x) * 8;
    float4 v0 = *reinterpret_cast<const float4*>(x + base);
    float4 v1 = *reinterpret_cast<const float4*>(x + base + 4);
    uint4 o;
    __half2 h;
    h = __floats2half2_rn(v0.x, v0.y); o.x = *reinterpret_cast<uint32_t*>(&h);
    h = __floats2half2_rn(v0.z, v0.w); o.y = *reinterpret_cast<uint32_t*>(&h);
    h = __floats2half2_rn(v1.x, v1.y); o.z = *reinterpret_cast<uint32_t*>(&h);
    h = __floats2half2_rn(v1.z, v1.w); o.w = *reinterpret_cast<uint32_t*>(&h);
    *reinterpret_cast<uint4*>(g_a + base) = o;
}

__device__ __forceinline__ void ldmat4(uint32_t addr, uint32_t& d0, uint32_t& d1,
                                       uint32_t& d2, uint32_t& d3) {
    asm volatile("ldmatrix.sync.aligned.m8n8.x4.shared.b16 {%0,%1,%2,%3}, [%4];\n"
                 : "=r"(d0), "=r"(d1), "=r"(d2), "=r"(d3) : "r"(addr));
}

__device__ __forceinline__ void mma16816(float* c, const uint32_t* a, const uint32_t* b) {
    asm volatile(
        "mma.sync.aligned.m16n8k16.row.col.f32.f16.f16.f32 "
        "{%0,%1,%2,%3}, {%4,%5,%6,%7}, {%8,%9}, {%0,%1,%2,%3};\n"
        : "+f"(c[0]), "+f"(c[1]), "+f"(c[2]), "+f"(c[3])
        : "r"(a[0]), "r"(a[1]), "r"(a[2]), "r"(a[3]), "r"(b[0]), "r"(b[1]));
}

__device__ __forceinline__ void cp16(uint32_t saddr, const void* gaddr) {
    asm volatile("cp.async.cg.shared.global [%0], [%1], 16;\n"
                 :: "r"(saddr), "l"(gaddr));
}

// ====== GEMM: 128(M) x 256(N) CTA, BK=64, 4-stage cp.async, pair loop =====
// One wait_group+__syncthreads per PAIR of chunks. smem rows: 128B,
// chunk ^= (row & 7): conflict-free for ldmatrix + writes.
#define BK 64
#define STAGES 4
#define NCH (DDIM / BK)
#define NPAIR (NCH / 2)
#define W_BYTES (256 * BK * 2)
#define A_BYTES (128 * BK * 2)
#define STAGE_BYTES (W_BYTES + A_BYTES)
#define SMEM_BYTES (STAGES * STAGE_BYTES)

template <int LAYER>
__global__ void __launch_bounds__(256, 1)
gemm_kernel(const float* __restrict__ bias, float* __restrict__ outf) {
    extern __shared__ char dsm[];
    const __half* __restrict__ A = (LAYER == 0) ? g_a : g_h;
    const __half* __restrict__ W = (LAYER == 0) ? g_w1 : g_w2;

    __shared__ float sBias[256];

    const int tid = threadIdx.x;
    const int lane = tid & 31;
    const int wid = tid >> 5;
    const int wm = wid & 1;
    const int wn = wid >> 1;
    const int o0 = blockIdx.x * 256;
    const int t0 = blockIdx.y * 128;

    sBias[tid] = __ldg(bias + o0 + tid);

    const uint32_t sdyn = (uint32_t)__cvta_generic_to_shared(dsm);

    // ---- coalesced loader maps: 8 threads cover one row's 128B ----
    const int lc = tid & 7;
    const int lr = tid >> 3;
    const __half* pW = W + (size_t)(o0 + lr) * DDIM + lc * 8;
    const __half* pA = A + (size_t)(t0 + lr) * DDIM + lc * 8;
    uint32_t stW[8], stA[4];
#pragma unroll
    for (int s = 0; s < 8; s++) {
        int row = lr + 32 * s;
        stW[s] = (uint32_t)(row * 128 + ((lc ^ (row & 7)) << 4));
    }
#pragma unroll
    for (int s = 0; s < 4; s++) {
        int row = lr + 32 * s;
        stA[s] = (uint32_t)(row * 128 + ((lc ^ (row & 7)) << 4));
    }

    // ---- mma fragment address components ----
    const int aRow = lane & 15;
    const int aKC = lane >> 4;
    const int bRow = (lane & 7) + ((lane >> 4) << 3);
    const int bKC = (lane >> 3) & 1;
    uint32_t aOff[4];
    int aXor[4];
#pragma unroll
    for (int mf = 0; mf < 4; mf++) {
        int row = wm * 64 + mf * 16 + aRow;
        aOff[mf] = (uint32_t)(row * 128);
        aXor[mf] = row & 7;
    }
    uint32_t bOff[4];
    int bXor[4];
#pragma unroll
    for (int nb = 0; nb < 4; nb++) {
        int row = wn * 64 + nb * 16 + bRow;
        bOff[nb] = (uint32_t)(row * 128);
        bXor[nb] = row & 7;
    }

    float acc[4][8][4];
#pragma unroll
    for (int i = 0; i < 4; i++)
#pragma unroll
        for (int j = 0; j < 8; j++)
#pragma unroll
            for (int k = 0; k < 4; k++) acc[i][j][k] = 0.f;

    // double-buffered fragments
    uint32_t af[2][4][4], bf[2][8][2];

    auto ldB = [&](int buf, uint32_t wb, int nb, int kc) {
        uint32_t addr = wb + bOff[nb] + (uint32_t)(((kc + bKC) ^ bXor[nb]) << 4);
        ldmat4(addr, bf[buf][nb * 2][0], bf[buf][nb * 2][1], bf[buf][nb * 2 + 1][0],
               bf[buf][nb * 2 + 1][1]);
    };
    auto ldA = [&](int buf, uint32_t ab, int mf, int kc) {
        uint32_t addr = ab + aOff[mf] + (uint32_t)(((kc + aKC) ^ aXor[mf]) << 4);
        ldmat4(addr, af[buf][mf][0], af[buf][mf][1], af[buf][mf][2], af[buf][mf][3]);
    };
    auto mma8 = [&](int mf, int buf) {
#pragma unroll
        for (int nf = 0; nf < 8; nf++) mma16816(acc[mf][nf], af[buf][mf], bf[buf][nf]);
    };

    // one chunk of the pair. cIdx: chunk being computed; ldIdx: chunk to load.
    // pairEnd: do wait_group+barrier in kstep3; haveNextFrag: preload next
    // chunk's kstep0 fragments (stage (cIdx+1)&3, already visible).
    auto chunk_body = [&](int cIdx, int ldIdx, bool doLoad, bool pairEnd,
                          bool haveNextFrag) {
        const uint32_t wb = sdyn + (cIdx & 3) * STAGE_BYTES;
        const uint32_t ab = wb + W_BYTES;
        const uint32_t wbL = sdyn + (ldIdx & 3) * STAGE_BYTES;
        const uint32_t abL = wbL + W_BYTES;
        const __half* pWL = pW + (size_t)ldIdx * BK;
        const __half* pAL = pA + (size_t)ldIdx * BK;

        // ksteps 0..2: load next-kstep frags + cp.async under MMA
#pragma unroll
        for (int j = 0; j < 3; j++) {
            const int cur = j & 1;
            const int nxt = cur ^ 1;
            const int kcN = 2 * (j + 1);
            ldB(nxt, wb, 0, kcN);
            ldB(nxt, wb, 1, kcN);
            mma8(0, cur);
            if (doLoad) {
                if (j < 2) {
                    cp16(wbL + stW[4 * j], pWL + (size_t)(4 * j) * 32 * DDIM);
                    cp16(wbL + stW[4 * j + 1], pWL + (size_t)(4 * j + 1) * 32 * DDIM);
                } else {
                    cp16(abL + stA[0], pAL);
                    cp16(abL + stA[1], pAL + (size_t)32 * DDIM);
                }
            }
            ldB(nxt, wb, 2, kcN);
            ldB(nxt, wb, 3, kcN);
            mma8(1, cur);
            if (doLoad) {
                if (j < 2) {
                    cp16(wbL + stW[4 * j + 2], pWL + (size_t)(4 * j + 2) * 32 * DDIM);
                    cp16(wbL + stW[4 * j + 3], pWL + (size_t)(4 * j + 3) * 32 * DDIM);
                } else {
                    cp16(abL + stA[2], pAL + (size_t)64 * DDIM);
                    cp16(abL + stA[3], pAL + (size_t)96 * DDIM);
                }
            }
            ldA(nxt, ab, 0, kcN);
            ldA(nxt, ab, 1, kcN);
            mma8(2, cur);
            ldA(nxt, ab, 2, kcN);
            ldA(nxt, ab, 3, kcN);
            mma8(3, cur);
            if (j == 2 && doLoad)
                asm volatile("cp.async.commit_group;\n" ::: "memory");
        }

        // kstep 3 (frags in buf1)
        mma8(0, 1);
        mma8(1, 1);
        if (pairEnd) {
            asm volatile("cp.async.wait_group 0;\n" ::: "memory");
            __syncthreads();
        }
        if (haveNextFrag) {
            const uint32_t wbn = sdyn + ((cIdx + 1) & 3) * STAGE_BYTES;
            const uint32_t abn = wbn + W_BYTES;
            ldB(0, wbn, 0, 0);
            ldB(0, wbn, 1, 0);
            mma8(2, 1);
            ldB(0, wbn, 2, 0);
            ldB(0, wbn, 3, 0);
            ldA(0, abn, 0, 0);
            ldA(0, abn, 1, 0);
            mma8(3, 1);
            ldA(0, abn, 2, 0);
            ldA(0, abn, 3, 0);
        } else {
            mma8(2, 1);
            mma8(3, 1);
        }
    };

    // prologue: load chunks 0,1; wait both; preload chunk0 kstep0 frags
    {
#pragma unroll
        for (int s = 0; s < 2; s++) {
            const uint32_t wb = sdyn + s * STAGE_BYTES;
            const uint32_t ab = wb + W_BYTES;
#pragma unroll
            for (int q = 0; q < 8; q++)
                cp16(wb + stW[q], pW + s * BK + (size_t)q * 32 * DDIM);
#pragma unroll
            for (int q = 0; q < 4; q++)
                cp16(ab + stA[q], pA + s * BK + (size_t)q * 32 * DDIM);
            asm volatile("cp.async.commit_group;\n" ::: "memory");
        }
        asm volatile("cp.async.wait_group 0;\n" ::: "memory");
        __syncthreads();
#pragma unroll
        for (int nb = 0; nb < 4; nb++) ldB(0, sdyn, nb, 0);
#pragma unroll
        for (int mf = 0; mf < 4; mf++) ldA(0, sdyn + W_BYTES, mf, 0);
    }

    for (int t = 0; t < NPAIR; t++) {
        const int c0 = 2 * t;
        const bool L = (t + 1 < NPAIR);
        chunk_body(c0, c0 + 2, L, false, true);
        chunk_body(c0 + 1, c0 + 3, L, true, L);
    }

    // ---- epilogue ----
    const int gr = lane >> 2;
    const int tc2 = (lane & 3) * 2;
#pragma unroll
    for (int mf = 0; mf < 4; mf++) {
        const int row = t0 + wm * 64 + mf * 16 + gr;
#pragma unroll
        for (int nf = 0; nf < 8; nf++) {
            const int colL = wn * 64 + nf * 8 + tc2;
            const int col = o0 + colL;
            float bv0 = sBias[colL];
            float bv1 = sBias[colL + 1];
            float v00 = acc[mf][nf][0] + bv0;
            float v01 = acc[mf][nf][1] + bv1;
            float v10 = acc[mf][nf][2] + bv0;
            float v11 = acc[mf][nf][3] + bv1;
            if (LAYER == 0) {
                *reinterpret_cast<__half2*>(g_h + (size_t)row * DDIM + col) =
                    __floats2half2_rn(v00, v01);
                *reinterpret_cast<__half2*>(g_h + (size_t)(row + 8) * DDIM + col) =
                    __floats2half2_rn(v10, v11);
            } else {
                *reinterpret_cast<float2*>(outf + (size_t)row * DDIM + col) =
                    make_float2(v00, v01);
                *reinterpret_cast<float2*>(outf + (size_t)(row + 8) * DDIM + col) =
                    make_float2(v10, v11);
            }
        }
    }
}

extern "C" void kernel_launch(void* const* d_in, const int* in_sizes, int n_in,
                              void* d_out, int out_size) {
    const float* x = (const float*)d_in[0];
    const int* w1c = (const int*)d_in[1];
    const float* w1s = (const float*)d_in[2];
    const float* b1 = (const float*)d_in[3];
    const int* w2c = (const int*)d_in[4];
    const float* w2s = (const float*)d_in[5];
    const float* b2 = (const float*)d_in[6];
    float* out = (float*)d_out;

    cudaFuncSetAttribute(gemm_kernel<0>, cudaFuncAttributeMaxDynamicSharedMemorySize,
                         SMEM_BYTES);
    cudaFuncSetAttribute(gemm_kernel<1>, cudaFuncAttributeMaxDynamicSharedMemorySize,
                         SMEM_BYTES);

    const int dq_blocks = ((size_t)DDIM * DDIM / 8) / 256;
    dequant_kernel<<<dq_blocks, 256>>>(w1c, w1s, 0);
    dequant_kernel<<<dq_blocks, 256>>>(w2c, w2s, 1);

    const int sp_blocks = ((size_t)TDIM * DDIM / 8) / 256;
    split_kernel<<<sp_blocks, 256>>>(x);

    dim3 grid(DDIM / 256, TDIM / 128);
    gemm_kernel<0><<<grid, 256, SMEM_BYTES>>>(b1, nullptr);
    gemm_kernel<1><<<grid, 256, SMEM_BYTES>>>(b2, out);
}

// round 12
// speedup vs baseline: 1.2440x; 1.2440x over previous
#include <cuda_runtime.h>
#include <cuda_fp16.h>
#include <cstdint>

#define TDIM 8192
#define DDIM 4096

// ---- device scratch (allocation-free rule: __device__ globals) ----
static __device__ __half g_w1[(size_t)DDIM * DDIM];
static __device__ __half g_w2[(size_t)DDIM * DDIM];
static __device__ __half g_a[(size_t)TDIM * DDIM];
static __device__ __half g_h[(size_t)TDIM * DDIM];

// ---- dequant: int32 codes [D,D] * 2^scales [D,D/32] -> fp16 [D,D] (exact) ----
__global__ void dequant_kernel(const int* __restrict__ codes,
                               const float* __restrict__ scales,
                               int which) {
    __half* __restrict__ out = which ? g_w2 : g_w1;
    size_t base = ((size_t)blockIdx.x * blockDim.x + threadIdx.x) * 8;
    const int4 c0 = *reinterpret_cast<const int4*>(codes + base);
    const int4 c1 = *reinterpret_cast<const int4*>(codes + base + 4);
    float s = __ldg(scales + (base >> 12) * (DDIM / 32) + ((base & 4095) >> 5));
    const __half2 hs2 = __half2half2(__float2half_rn(s));

    uint4 o;
    {
        uint32_t sel = (c0.x & 7) | ((c0.y & 7) << 4) | ((c0.z & 7) << 8) |
                       ((c0.w & 7) << 12);
        uint32_t hb = __byte_perm(0x3E3C3800u, 0x46444240u, sel);
        uint32_t p0 = __byte_perm(hb, 0, 0x1404) |
                      ((c0.x & 8) << 12) | ((c0.y & 8) << 28);
        uint32_t p1 = __byte_perm(hb, 0, 0x3424) |
                      ((c0.z & 8) << 12) | ((c0.w & 8) << 28);
        __half2 r0 = __hmul2(*reinterpret_cast<__half2*>(&p0), hs2);
        __half2 r1 = __hmul2(*reinterpret_cast<__half2*>(&p1), hs2);
        o.x = *reinterpret_cast<uint32_t*>(&r0);
        o.y = *reinterpret_cast<uint32_t*>(&r1);
    }
    {
        uint32_t sel = (c1.x & 7) | ((c1.y & 7) << 4) | ((c1.z & 7) << 8) |
                       ((c1.w & 7) << 12);
        uint32_t hb = __byte_perm(0x3E3C3800u, 0x46444240u, sel);
        uint32_t p0 = __byte_perm(hb, 0, 0x1404) |
                      ((c1.x & 8) << 12) | ((c1.y & 8) << 28);
        uint32_t p1 = __byte_perm(hb, 0, 0x3424) |
                      ((c1.z & 8) << 12) | ((c1.w & 8) << 28);
        __half2 r0 = __hmul2(*reinterpret_cast<__half2*>(&p0), hs2);
        __half2 r1 = __hmul2(*reinterpret_cast<__half2*>(&p1), hs2);
        o.z = *reinterpret_cast<uint32_t*>(&r0);
        o.w = *reinterpret_cast<uint32_t*>(&r1);
    }
    *reinterpret_cast<uint4*>(out + base) = o;
}

// ---- convert fp32 x -> fp16, 8 elems/thread ----
__global__ void split_kernel(const float* __restrict__ x) {
    size_t base = ((size_t)blockIdx.x * blockDim.x + threadIdx.x) * 8;
    float4 v0 = *reinterpret_cast<const float4*>(x + base);
    float4 v1 = *reinterpret_cast<const float4*>(x + base + 4);
    uint4 o;
    __half2 h;
    h = __floats2half2_rn(v0.x, v0.y); o.x = *reinterpret_cast<uint32_t*>(&h);
    h = __floats2half2_rn(v0.z, v0.w); o.y = *reinterpret_cast<uint32_t*>(&h);
    h = __floats2half2_rn(v1.x, v1.y); o.z = *reinterpret_cast<uint32_t*>(&h);
    h = __floats2half2_rn(v1.z, v1.w); o.w = *reinterpret_cast<uint32_t*>(&h);
    *reinterpret_cast<uint4*>(g_a + base) = o;
}

__device__ __forceinline__ void ldmat4(uint32_t addr, uint32_t& d0, uint32_t& d1,
                                       uint32_t& d2, uint32_t& d3) {
    asm volatile("ldmatrix.sync.aligned.m8n8.x4.shared.b16 {%0,%1,%2,%3}, [%4];\n"
                 : "=r"(d0), "=r"(d1), "=r"(d2), "=r"(d3) : "r"(addr));
}

__device__ __forceinline__ void mma16816(float* c, const uint32_t* a, const uint32_t* b) {
    asm volatile(
        "mma.sync.aligned.m16n8k16.row.col.f32.f16.f16.f32 "
        "{%0,%1,%2,%3}, {%4,%5,%6,%7}, {%8,%9}, {%0,%1,%2,%3};\n"
        : "+f"(c[0]), "+f"(c[1]), "+f"(c[2]), "+f"(c[3])
        : "r"(a[0]), "r"(a[1]), "r"(a[2]), "r"(a[3]), "r"(b[0]), "r"(b[1]));
}

__device__ __forceinline__ void cp16(uint32_t saddr, const void* gaddr) {
    asm volatile("cp.async.cg.shared.global [%0], [%1], 16;\n"
                 :: "r"(saddr), "l"(gaddr));
}

// ====== GEMM: 128(M) x 128(N) CTA, 128 threads, 2 CTAs/SM, BK=64, 3 stages =
// 4 warps = 2(M) x 2(N), 64x64 per warp. Same per-chunk schedule as R10;
// two independent CTAs per SM decouple the barrier convoy.
// smem rows: 128B, chunk ^= (row & 7): conflict-free ldmatrix + writes.
#define BK 64
#define STAGES 3
#define NCH (DDIM / BK)
#define W_BYTES (128 * BK * 2)
#define A_BYTES (128 * BK * 2)
#define STAGE_BYTES (W_BYTES + A_BYTES)
#define SMEM_BYTES (STAGES * STAGE_BYTES)

template <int LAYER>
__global__ void __launch_bounds__(128, 2)
gemm_kernel(const float* __restrict__ bias, float* __restrict__ outf) {
    extern __shared__ char dsm[];
    const __half* __restrict__ A = (LAYER == 0) ? g_a : g_h;
    const __half* __restrict__ W = (LAYER == 0) ? g_w1 : g_w2;

    __shared__ float sBias[128];

    const int tid = threadIdx.x;
    const int lane = tid & 31;
    const int wid = tid >> 5;
    const int wm = wid & 1;   // 2 warps along M
    const int wn = wid >> 1;  // 2 warps along N
    const int o0 = blockIdx.x * 128;
    const int t0 = blockIdx.y * 128;

    sBias[tid] = __ldg(bias + o0 + tid);

    const uint32_t sdyn = (uint32_t)__cvta_generic_to_shared(dsm);

    // ---- coalesced loader maps: 8 threads cover one row's 128B ----
    const int lc = tid & 7;
    const int lr = tid >> 3;  // 0..15, sweeps add 16
    const __half* pW = W + (size_t)(o0 + lr) * DDIM + lc * 8;
    const __half* pA = A + (size_t)(t0 + lr) * DDIM + lc * 8;
    uint32_t stW[8], stA[8];
#pragma unroll
    for (int s = 0; s < 8; s++) {
        int row = lr + 16 * s;
        uint32_t off = (uint32_t)(row * 128 + ((lc ^ (row & 7)) << 4));
        stW[s] = off;
        stA[s] = off;
    }

    // ---- mma fragment address components ----
    const int aRow = lane & 15;
    const int aKC = lane >> 4;
    const int bRow = (lane & 7) + ((lane >> 4) << 3);
    const int bKC = (lane >> 3) & 1;
    uint32_t aOff[4];
    int aXor[4];
#pragma unroll
    for (int mf = 0; mf < 4; mf++) {
        int row = wm * 64 + mf * 16 + aRow;
        aOff[mf] = (uint32_t)(row * 128);
        aXor[mf] = row & 7;
    }
    uint32_t bOff[4];
    int bXor[4];
#pragma unroll
    for (int nb = 0; nb < 4; nb++) {
        int row = wn * 64 + nb * 16 + bRow;
        bOff[nb] = (uint32_t)(row * 128);
        bXor[nb] = row & 7;
    }

    float acc[4][8][4];
#pragma unroll
    for (int i = 0; i < 4; i++)
#pragma unroll
        for (int j = 0; j < 8; j++)
#pragma unroll
            for (int k = 0; k < 4; k++) acc[i][j][k] = 0.f;

    // double-buffered fragments
    uint32_t af[2][4][4], bf[2][8][2];

    auto ldB = [&](int buf, uint32_t wb, int nb, int kc) {
        uint32_t addr = wb + bOff[nb] + (uint32_t)(((kc + bKC) ^ bXor[nb]) << 4);
        ldmat4(addr, bf[buf][nb * 2][0], bf[buf][nb * 2][1], bf[buf][nb * 2 + 1][0],
               bf[buf][nb * 2 + 1][1]);
    };
    auto ldA = [&](int buf, uint32_t ab, int mf, int kc) {
        uint32_t addr = ab + aOff[mf] + (uint32_t)(((kc + aKC) ^ aXor[mf]) << 4);
        ldmat4(addr, af[buf][mf][0], af[buf][mf][1], af[buf][mf][2], af[buf][mf][3]);
    };
    auto mma8 = [&](int mf, int buf) {
#pragma unroll
        for (int nf = 0; nf < 8; nf++) mma16816(acc[mf][nf], af[buf][mf], bf[buf][nf]);
    };

    // full-stage loader (prologue only): 8 W sweeps + 8 A sweeps, 16-row stride
    auto load_stage = [&](int s, int k0) {
        const uint32_t wb = sdyn + s * STAGE_BYTES;
        const uint32_t ab = wb + W_BYTES;
#pragma unroll
        for (int q = 0; q < 8; q++)
            cp16(wb + stW[q], pW + k0 + (size_t)q * 16 * DDIM);
#pragma unroll
        for (int q = 0; q < 8; q++)
            cp16(ab + stA[q], pA + k0 + (size_t)q * 16 * DDIM);
        asm volatile("cp.async.commit_group;\n" ::: "memory");
    };

    // prologue: chunks 0,1 in flight; wait chunk0; preload kstep0 frags (buf0)
    load_stage(0, 0);
    load_stage(1, BK);
    asm volatile("cp.async.wait_group 1;\n" ::: "memory");
    __syncthreads();
#pragma unroll
    for (int nb = 0; nb < 4; nb++) ldB(0, sdyn, nb, 0);
#pragma unroll
    for (int mf = 0; mf < 4; mf++) ldA(0, sdyn + W_BYTES, mf, 0);

    for (int i = 0; i < NCH; i++) {
        const uint32_t wb = sdyn + (i % STAGES) * STAGE_BYTES;
        const uint32_t ab = wb + W_BYTES;
        const uint32_t wbn = sdyn + ((i + 1) % STAGES) * STAGE_BYTES;
        const uint32_t abn = wbn + W_BYTES;
        const uint32_t wbL = sdyn + ((i + 2) % STAGES) * STAGE_BYTES;
        const uint32_t abL = wbL + W_BYTES;
        const __half* pWL = pW + (size_t)(i + 2) * BK;
        const __half* pAL = pA + (size_t)(i + 2) * BK;
        const bool haveNext = (i + 1 < NCH);
        const bool load2 = (i + 2 < NCH);

        // ---- ksteps 0..2: next-kstep frags + 16 cp.async spread under MMA ----
#pragma unroll
        for (int j = 0; j < 3; j++) {
            const int cur = j & 1;
            const int nxt = cur ^ 1;
            const int kcN = 2 * (j + 1);
            ldB(nxt, wb, 0, kcN);
            ldB(nxt, wb, 1, kcN);
            mma8(0, cur);
            if (load2) {
                if (j == 0) {
                    cp16(wbL + stW[0], pWL);
                    cp16(wbL + stW[1], pWL + (size_t)16 * DDIM);
                    cp16(wbL + stW[2], pWL + (size_t)32 * DDIM);
                } else if (j == 1) {
                    cp16(wbL + stW[6], pWL + (size_t)96 * DDIM);
                    cp16(wbL + stW[7], pWL + (size_t)112 * DDIM);
                    cp16(abL + stA[0], pAL);
                } else {
                    cp16(abL + stA[4], pAL + (size_t)64 * DDIM);
                    cp16(abL + stA[5], pAL + (size_t)80 * DDIM);
                }
            }
            ldB(nxt, wb, 2, kcN);
            ldB(nxt, wb, 3, kcN);
            mma8(1, cur);
            if (load2) {
                if (j == 0) {
                    cp16(wbL + stW[3], pWL + (size_t)48 * DDIM);
                    cp16(wbL + stW[4], pWL + (size_t)64 * DDIM);
                    cp16(wbL + stW[5], pWL + (size_t)80 * DDIM);
                } else if (j == 1) {
                    cp16(abL + stA[1], pAL + (size_t)16 * DDIM);
                    cp16(abL + stA[2], pAL + (size_t)32 * DDIM);
                    cp16(abL + stA[3], pAL + (size_t)48 * DDIM);
                } else {
                    cp16(abL + stA[6], pAL + (size_t)96 * DDIM);
                    cp16(abL + stA[7], pAL + (size_t)112 * DDIM);
                }
            }
            ldA(nxt, ab, 0, kcN);
            ldA(nxt, ab, 1, kcN);
            mma8(2, cur);
            ldA(nxt, ab, 2, kcN);
            ldA(nxt, ab, 3, kcN);
            mma8(3, cur);
            if (j == 2 && load2)
                asm volatile("cp.async.commit_group;\n" ::: "memory");
        }

        // ---- kstep 3 (frags in buf1): barrier mid-burst, preload next chunk ----
        mma8(0, 1);
        mma8(1, 1);
        if (load2)
            asm volatile("cp.async.wait_group 1;\n" ::: "memory");
        else
            asm volatile("cp.async.wait_group 0;\n" ::: "memory");
        __syncthreads();
        if (haveNext) {
            ldB(0, wbn, 0, 0);
            ldB(0, wbn, 1, 0);
        }
        mma8(2, 1);
        if (haveNext) {
            ldB(0, wbn, 2, 0);
            ldB(0, wbn, 3, 0);
            ldA(0, abn, 0, 0);
            ldA(0, abn, 1, 0);
        }
        mma8(3, 1);
        if (haveNext) {
            ldA(0, abn, 2, 0);
            ldA(0, abn, 3, 0);
        }
    }

    // ---- epilogue ----
    const int gr = lane >> 2;
    const int tc2 = (lane & 3) * 2;
#pragma unroll
    for (int mf = 0; mf < 4; mf++) {
        const int row = t0 + wm * 64 + mf * 16 + gr;
#pragma unroll
        for (int nf = 0; nf < 8; nf++) {
            const int colL = wn * 64 + nf * 8 + tc2;
            const int col = o0 + colL;
            float bv0 = sBias[colL];
            float bv1 = sBias[colL + 1];
            float v00 = acc[mf][nf][0] + bv0;
            float v01 = acc[mf][nf][1] + bv1;
            float v10 = acc[mf][nf][2] + bv0;
            float v11 = acc[mf][nf][3] + bv1;
            if (LAYER == 0) {
                *reinterpret_cast<__half2*>(g_h + (size_t)row * DDIM + col) =
                    __floats2half2_rn(v00, v01);
                *reinterpret_cast<__half2*>(g_h + (size_t)(row + 8) * DDIM + col) =
                    __floats2half2_rn(v10, v11);
            } else {
                *reinterpret_cast<float2*>(outf + (size_t)row * DDIM + col) =
                    make_float2(v00, v01);
                *reinterpret_cast<float2*>(outf + (size_t)(row + 8) * DDIM + col) =
                    make_float2(v10, v11);
            }
        }
    }
}

extern "C" void kernel_launch(void* const* d_in, const int* in_sizes, int n_in,
                              void* d_out, int out_size) {
    const float* x = (const float*)d_in[0];
    const int* w1c = (const int*)d_in[1];
    const float* w1s = (const float*)d_in[2];
    const float* b1 = (const float*)d_in[3];
    const int* w2c = (const int*)d_in[4];
    const float* w2s = (const float*)d_in[5];
    const float* b2 = (const float*)d_in[6];
    float* out = (float*)d_out;

    cudaFuncSetAttribute(gemm_kernel<0>, cudaFuncAttributeMaxDynamicSharedMemorySize,
                         SMEM_BYTES);
    cudaFuncSetAttribute(gemm_kernel<1>, cudaFuncAttributeMaxDynamicSharedMemorySize,
                         SMEM_BYTES);

    const int dq_blocks = ((size_t)DDIM * DDIM / 8) / 256;
    dequant_kernel<<<dq_blocks, 256>>>(w1c, w1s, 0);
    dequant_kernel<<<dq_blocks, 256>>>(w2c, w2s, 1);

    const int sp_blocks = ((size_t)TDIM * DDIM / 8) / 256;
    split_kernel<<<sp_blocks, 256>>>(x);

    dim3 grid(DDIM / 128, TDIM / 128);
    gemm_kernel<0><<<grid, 128, SMEM_BYTES>>>(b1, nullptr);
    gemm_kernel<1><<<grid, 128, SMEM_BYTES>>>(b2, out);
}

// round 13
// speedup vs baseline: 1.2532x; 1.0073x over previous
#include <cuda_runtime.h>
#include <cuda_fp16.h>
#include <cstdint>

#define TDIM 8192
#define DDIM 4096

// ---- device scratch (allocation-free rule: __device__ globals) ----
static __device__ __half g_w1[(size_t)DDIM * DDIM];
static __device__ __half g_w2[(size_t)DDIM * DDIM];
static __device__ __half g_a[(size_t)TDIM * DDIM];
static __device__ __half g_h[(size_t)TDIM * DDIM];

// E2M1 decode via PRMT: positive magnitudes {0,.5,1,1.5,2,3,4,6} have fp16
// high bytes {00,38,3C,3E,40,42,44,46}; sign = code bit 3. Scale is a power
// of two in [2^-6, 2^1]; fp16 multiply is exact here.
__device__ __forceinline__ void dequant8(const int* __restrict__ codes,
                                         const float* __restrict__ scales,
                                         __half* __restrict__ out,
                                         size_t base) {
    const int4 c0 = *reinterpret_cast<const int4*>(codes + base);
    const int4 c1 = *reinterpret_cast<const int4*>(codes + base + 4);
    float s = __ldg(scales + (base >> 12) * (DDIM / 32) + ((base & 4095) >> 5));
    const __half2 hs2 = __half2half2(__float2half_rn(s));
    uint4 o;
    {
        uint32_t sel = (c0.x & 7) | ((c0.y & 7) << 4) | ((c0.z & 7) << 8) |
                       ((c0.w & 7) << 12);
        uint32_t hb = __byte_perm(0x3E3C3800u, 0x46444240u, sel);
        uint32_t p0 = __byte_perm(hb, 0, 0x1404) |
                      ((c0.x & 8) << 12) | ((c0.y & 8) << 28);
        uint32_t p1 = __byte_perm(hb, 0, 0x3424) |
                      ((c0.z & 8) << 12) | ((c0.w & 8) << 28);
        __half2 r0 = __hmul2(*reinterpret_cast<__half2*>(&p0), hs2);
        __half2 r1 = __hmul2(*reinterpret_cast<__half2*>(&p1), hs2);
        o.x = *reinterpret_cast<uint32_t*>(&r0);
        o.y = *reinterpret_cast<uint32_t*>(&r1);
    }
    {
        uint32_t sel = (c1.x & 7) | ((c1.y & 7) << 4) | ((c1.z & 7) << 8) |
                       ((c1.w & 7) << 12);
        uint32_t hb = __byte_perm(0x3E3C3800u, 0x46444240u, sel);
        uint32_t p0 = __byte_perm(hb, 0, 0x1404) |
                      ((c1.x & 8) << 12) | ((c1.y & 8) << 28);
        uint32_t p1 = __byte_perm(hb, 0, 0x3424) |
                      ((c1.z & 8) << 12) | ((c1.w & 8) << 28);
        __half2 r0 = __hmul2(*reinterpret_cast<__half2*>(&p0), hs2);
        __half2 r1 = __hmul2(*reinterpret_cast<__half2*>(&p1), hs2);
        o.z = *reinterpret_cast<uint32_t*>(&r0);
        o.w = *reinterpret_cast<uint32_t*>(&r1);
    }
    *reinterpret_cast<uint4*>(out + base) = o;
}

// ---- single fused aux kernel: dequant W1, dequant W2, convert x ----
#define DQ_BLOCKS ((DDIM * (size_t)DDIM / 8) / 256)   // 8192
#define SP_BLOCKS ((TDIM * (size_t)DDIM / 8) / 256)   // 16384
__global__ void aux_kernel(const int* __restrict__ w1c, const float* __restrict__ w1s,
                           const int* __restrict__ w2c, const float* __restrict__ w2s,
                           const float* __restrict__ x) {
    const size_t b = blockIdx.x;
    if (b < DQ_BLOCKS) {
        dequant8(w1c, w1s, g_w1, (b * 256 + threadIdx.x) * 8);
    } else if (b < 2 * DQ_BLOCKS) {
        dequant8(w2c, w2s, g_w2, ((b - DQ_BLOCKS) * 256 + threadIdx.x) * 8);
    } else {
        size_t base = ((b - 2 * DQ_BLOCKS) * 256 + threadIdx.x) * 8;
        float4 v0 = *reinterpret_cast<const float4*>(x + base);
        float4 v1 = *reinterpret_cast<const float4*>(x + base + 4);
        uint4 o;
        __half2 h;
        h = __floats2half2_rn(v0.x, v0.y); o.x = *reinterpret_cast<uint32_t*>(&h);
        h = __floats2half2_rn(v0.z, v0.w); o.y = *reinterpret_cast<uint32_t*>(&h);
        h = __floats2half2_rn(v1.x, v1.y); o.z = *reinterpret_cast<uint32_t*>(&h);
        h = __floats2half2_rn(v1.z, v1.w); o.w = *reinterpret_cast<uint32_t*>(&h);
        *reinterpret_cast<uint4*>(g_a + base) = o;
    }
}

__device__ __forceinline__ void ldmat4(uint32_t addr, uint32_t& d0, uint32_t& d1,
                                       uint32_t& d2, uint32_t& d3) {
    asm volatile("ldmatrix.sync.aligned.m8n8.x4.shared.b16 {%0,%1,%2,%3}, [%4];\n"
                 : "=r"(d0), "=r"(d1), "=r"(d2), "=r"(d3) : "r"(addr));
}

__device__ __forceinline__ void mma16816(float* c, const uint32_t* a, const uint32_t* b) {
    asm volatile(
        "mma.sync.aligned.m16n8k16.row.col.f32.f16.f16.f32 "
        "{%0,%1,%2,%3}, {%4,%5,%6,%7}, {%8,%9}, {%0,%1,%2,%3};\n"
        : "+f"(c[0]), "+f"(c[1]), "+f"(c[2]), "+f"(c[3])
        : "r"(a[0]), "r"(a[1]), "r"(a[2]), "r"(a[3]), "r"(b[0]), "r"(b[1]));
}

__device__ __forceinline__ void cp16(uint32_t saddr, const void* gaddr) {
    asm volatile("cp.async.cg.shared.global [%0], [%1], 16;\n"
                 :: "r"(saddr), "l"(gaddr));
}

// ====== GEMM: 128(M) x 128(N) CTA, 128 threads, 2 CTAs/SM, BK=64, 3 stages =
// 4 warps = 2(M) x 2(N), 64x64 per warp. Rotating stage offsets (no %).
// smem rows: 128B, chunk ^= (row & 7): conflict-free ldmatrix + writes.
#define BK 64
#define STAGES 3
#define NCH (DDIM / BK)
#define W_BYTES (128 * BK * 2)
#define A_BYTES (128 * BK * 2)
#define STAGE_BYTES (W_BYTES + A_BYTES)
#define SMEM_BYTES (STAGES * STAGE_BYTES)

template <int LAYER>
__global__ void __launch_bounds__(128, 2)
gemm_kernel(const float* __restrict__ bias, float* __restrict__ outf) {
    extern __shared__ char dsm[];
    const __half* __restrict__ A = (LAYER == 0) ? g_a : g_h;
    const __half* __restrict__ W = (LAYER == 0) ? g_w1 : g_w2;

    __shared__ float sBias[128];

    const int tid = threadIdx.x;
    const int lane = tid & 31;
    const int wid = tid >> 5;
    const int wm = wid & 1;
    const int wn = wid >> 1;
    const int o0 = blockIdx.x * 128;
    const int t0 = blockIdx.y * 128;

    sBias[tid] = __ldg(bias + o0 + tid);

    const uint32_t sdyn = (uint32_t)__cvta_generic_to_shared(dsm);

    // ---- coalesced loader maps: 8 threads cover one row's 128B ----
    const int lc = tid & 7;
    const int lr = tid >> 3;
    const __half* pW = W + (size_t)(o0 + lr) * DDIM + lc * 8;
    const __half* pA = A + (size_t)(t0 + lr) * DDIM + lc * 8;
    uint32_t st[8];
#pragma unroll
    for (int s = 0; s < 8; s++) {
        int row = lr + 16 * s;
        st[s] = (uint32_t)(row * 128 + ((lc ^ (row & 7)) << 4));
    }

    // ---- mma fragment address components ----
    const int aRow = lane & 15;
    const int aKC = lane >> 4;
    const int bRow = (lane & 7) + ((lane >> 4) << 3);
    const int bKC = (lane >> 3) & 1;
    uint32_t aOff[4];
    int aXor[4];
#pragma unroll
    for (int mf = 0; mf < 4; mf++) {
        int row = wm * 64 + mf * 16 + aRow;
        aOff[mf] = (uint32_t)(row * 128);
        aXor[mf] = row & 7;
    }
    uint32_t bOff[4];
    int bXor[4];
#pragma unroll
    for (int nb = 0; nb < 4; nb++) {
        int row = wn * 64 + nb * 16 + bRow;
        bOff[nb] = (uint32_t)(row * 128);
        bXor[nb] = row & 7;
    }

    float acc[4][8][4];
#pragma unroll
    for (int i = 0; i < 4; i++)
#pragma unroll
        for (int j = 0; j < 8; j++)
#pragma unroll
            for (int k = 0; k < 4; k++) acc[i][j][k] = 0.f;

    // double-buffered fragments
    uint32_t af[2][4][4], bf[2][8][2];

    auto ldB = [&](int buf, uint32_t wb, int nb, int kc) {
        uint32_t addr = wb + bOff[nb] + (uint32_t)(((kc + bKC) ^ bXor[nb]) << 4);
        ldmat4(addr, bf[buf][nb * 2][0], bf[buf][nb * 2][1], bf[buf][nb * 2 + 1][0],
               bf[buf][nb * 2 + 1][1]);
    };
    auto ldA = [&](int buf, uint32_t ab, int mf, int kc) {
        uint32_t addr = ab + aOff[mf] + (uint32_t)(((kc + aKC) ^ aXor[mf]) << 4);
        ldmat4(addr, af[buf][mf][0], af[buf][mf][1], af[buf][mf][2], af[buf][mf][3]);
    };
    auto mma8 = [&](int mf, int buf) {
#pragma unroll
        for (int nf = 0; nf < 8; nf++) mma16816(acc[mf][nf], af[buf][mf], bf[buf][nf]);
    };

    // full-stage loader (prologue only)
    auto load_stage = [&](uint32_t wb, int k0) {
        const uint32_t ab = wb + W_BYTES;
#pragma unroll
        for (int q = 0; q < 8; q++)
            cp16(wb + st[q], pW + k0 + (size_t)q * 16 * DDIM);
#pragma unroll
        for (int q = 0; q < 8; q++)
            cp16(ab + st[q], pA + k0 + (size_t)q * 16 * DDIM);
        asm volatile("cp.async.commit_group;\n" ::: "memory");
    };

    // prologue: chunks 0,1 in flight; wait chunk0; preload kstep0 frags (buf0)
    load_stage(sdyn, 0);
    load_stage(sdyn + STAGE_BYTES, BK);
    asm volatile("cp.async.wait_group 1;\n" ::: "memory");
    __syncthreads();
#pragma unroll
    for (int nb = 0; nb < 4; nb++) ldB(0, sdyn, nb, 0);
#pragma unroll
    for (int mf = 0; mf < 4; mf++) ldA(0, sdyn + W_BYTES, mf, 0);

    // rotating stage bases: wb = compute, wbn = next (visible), wbL = load dst
    uint32_t wb = sdyn;
    uint32_t wbn = sdyn + STAGE_BYTES;
    uint32_t wbL = sdyn + 2 * STAGE_BYTES;
    const __half* pWL = pW + 2 * BK;
    const __half* pAL = pA + 2 * BK;

#pragma unroll 1
    for (int i = 0; i < NCH; i++) {
        const uint32_t ab = wb + W_BYTES;
        const uint32_t abn = wbn + W_BYTES;
        const uint32_t abL = wbL + W_BYTES;
        const bool haveNext = (i + 1 < NCH);
        const bool load2 = (i + 2 < NCH);

        // ---- ksteps 0..2: next-kstep frags + 16 cp.async spread under MMA ----
#pragma unroll
        for (int j = 0; j < 3; j++) {
            const int cur = j & 1;
            const int nxt = cur ^ 1;
            const int kcN = 2 * (j + 1);
            ldB(nxt, wb, 0, kcN);
            ldB(nxt, wb, 1, kcN);
            mma8(0, cur);
            if (load2) {
                if (j == 0) {
                    cp16(wbL + st[0], pWL);
                    cp16(wbL + st[1], pWL + (size_t)16 * DDIM);
                    cp16(wbL + st[2], pWL + (size_t)32 * DDIM);
                } else if (j == 1) {
                    cp16(wbL + st[6], pWL + (size_t)96 * DDIM);
                    cp16(wbL + st[7], pWL + (size_t)112 * DDIM);
                    cp16(abL + st[0], pAL);
                } else {
                    cp16(abL + st[4], pAL + (size_t)64 * DDIM);
                    cp16(abL + st[5], pAL + (size_t)80 * DDIM);
                }
            }
            ldB(nxt, wb, 2, kcN);
            ldB(nxt, wb, 3, kcN);
            mma8(1, cur);
            if (load2) {
                if (j == 0) {
                    cp16(wbL + st[3], pWL + (size_t)48 * DDIM);
                    cp16(wbL + st[4], pWL + (size_t)64 * DDIM);
                    cp16(wbL + st[5], pWL + (size_t)80 * DDIM);
                } else if (j == 1) {
                    cp16(abL + st[1], pAL + (size_t)16 * DDIM);
                    cp16(abL + st[2], pAL + (size_t)32 * DDIM);
                    cp16(abL + st[3], pAL + (size_t)48 * DDIM);
                } else {
                    cp16(abL + st[6], pAL + (size_t)96 * DDIM);
                    cp16(abL + st[7], pAL + (size_t)112 * DDIM);
                }
            }
            ldA(nxt, ab, 0, kcN);
            ldA(nxt, ab, 1, kcN);
            mma8(2, cur);
            ldA(nxt, ab, 2, kcN);
            ldA(nxt, ab, 3, kcN);
            mma8(3, cur);
            if (j == 2 && load2)
                asm volatile("cp.async.commit_group;\n" ::: "memory");
        }

        // ---- kstep 3 (frags in buf1): barrier mid-burst, preload next chunk ----
        mma8(0, 1);
        mma8(1, 1);
        if (load2)
            asm volatile("cp.async.wait_group 1;\n" ::: "memory");
        else
            asm volatile("cp.async.wait_group 0;\n" ::: "memory");
        __syncthreads();
        if (haveNext) {
            ldB(0, wbn, 0, 0);
            ldB(0, wbn, 1, 0);
        }
        mma8(2, 1);
        if (haveNext) {
            ldB(0, wbn, 2, 0);
            ldB(0, wbn, 3, 0);
            ldA(0, abn, 0, 0);
            ldA(0, abn, 1, 0);
        }
        mma8(3, 1);
        if (haveNext) {
            ldA(0, abn, 2, 0);
            ldA(0, abn, 3, 0);
        }

        // rotate stages, advance load pointers
        uint32_t tmp = wb;
        wb = wbn;
        wbn = wbL;
        wbL = tmp;
        pWL += BK;
        pAL += BK;
    }

    // ---- epilogue ----
    const int gr = lane >> 2;
    const int tc2 = (lane & 3) * 2;
#pragma unroll
    for (int mf = 0; mf < 4; mf++) {
        const int row = t0 + wm * 64 + mf * 16 + gr;
#pragma unroll
        for (int nf = 0; nf < 8; nf++) {
            const int colL = wn * 64 + nf * 8 + tc2;
            const int col = o0 + colL;
            float bv0 = sBias[colL];
            float bv1 = sBias[colL + 1];
            float v00 = acc[mf][nf][0] + bv0;
            float v01 = acc[mf][nf][1] + bv1;
            float v10 = acc[mf][nf][2] + bv0;
            float v11 = acc[mf][nf][3] + bv1;
            if (LAYER == 0) {
                *reinterpret_cast<__half2*>(g_h + (size_t)row * DDIM + col) =
                    __floats2half2_rn(v00, v01);
                *reinterpret_cast<__half2*>(g_h + (size_t)(row + 8) * DDIM + col) =
                    __floats2half2_rn(v10, v11);
            } else {
                *reinterpret_cast<float2*>(outf + (size_t)row * DDIM + col) =
                    make_float2(v00, v01);
                *reinterpret_cast<float2*>(outf + (size_t)(row + 8) * DDIM + col) =
                    make_float2(v10, v11);
            }
        }
    }
}

extern "C" void kernel_launch(void* const* d_in, const int* in_sizes, int n_in,
                              void* d_out, int out_size) {
    const float* x = (const float*)d_in[0];
    const int* w1c = (const int*)d_in[1];
    const float* w1s = (const float*)d_in[2];
    const float* b1 = (const float*)d_in[3];
    const int* w2c = (const int*)d_in[4];
    const float* w2s = (const float*)d_in[5];
    const float* b2 = (const float*)d_in[6];
    float* out = (float*)d_out;

    cudaFuncSetAttribute(gemm_kernel<0>, cudaFuncAttributeMaxDynamicSharedMemorySize,
                         SMEM_BYTES);
    cudaFuncSetAttribute(gemm_kernel<1>, cudaFuncAttributeMaxDynamicSharedMemorySize,
                         SMEM_BYTES);

    aux_kernel<<<(unsigned)(2 * DQ_BLOCKS + SP_BLOCKS), 256>>>(w1c, w1s, w2c, w2s, x);

    dim3 grid(DDIM / 128, TDIM / 128);
    gemm_kernel<0><<<grid, 128, SMEM_BYTES>>>(b1, nullptr);
    gemm_kernel<1><<<grid, 128, SMEM_BYTES>>>(b2, out);
}

// round 14
// speedup vs baseline: 1.2608x; 1.0061x over previous
#include <cuda_runtime.h>
#include <cuda_fp16.h>
#include <cstdint>

#define TDIM 8192
#define DDIM 4096

// ---- device scratch (allocation-free rule: __device__ globals) ----
static __device__ __half g_w1[(size_t)DDIM * DDIM];
static __device__ __half g_w2[(size_t)DDIM * DDIM];
static __device__ __half g_a[(size_t)TDIM * DDIM];
static __device__ __half g_h[(size_t)TDIM * DDIM];

// E2M1 decode via PRMT: positive magnitudes {0,.5,1,1.5,2,3,4,6} have fp16
// high bytes {00,38,3C,3E,40,42,44,46}; sign = code bit 3. Scale is a power
// of two in [2^-6, 2^1]; fp16 multiply is exact here.
__device__ __forceinline__ void dequant8(const int* __restrict__ codes,
                                         const float* __restrict__ scales,
                                         __half* __restrict__ out,
                                         size_t base) {
    const int4 c0 = *reinterpret_cast<const int4*>(codes + base);
    const int4 c1 = *reinterpret_cast<const int4*>(codes + base + 4);
    float s = __ldg(scales + (base >> 12) * (DDIM / 32) + ((base & 4095) >> 5));
    const __half2 hs2 = __half2half2(__float2half_rn(s));
    uint4 o;
    {
        uint32_t sel = (c0.x & 7) | ((c0.y & 7) << 4) | ((c0.z & 7) << 8) |
                       ((c0.w & 7) << 12);
        uint32_t hb = __byte_perm(0x3E3C3800u, 0x46444240u, sel);
        uint32_t p0 = __byte_perm(hb, 0, 0x1404) |
                      ((c0.x & 8) << 12) | ((c0.y & 8) << 28);
        uint32_t p1 = __byte_perm(hb, 0, 0x3424) |
                      ((c0.z & 8) << 12) | ((c0.w & 8) << 28);
        __half2 r0 = __hmul2(*reinterpret_cast<__half2*>(&p0), hs2);
        __half2 r1 = __hmul2(*reinterpret_cast<__half2*>(&p1), hs2);
        o.x = *reinterpret_cast<uint32_t*>(&r0);
        o.y = *reinterpret_cast<uint32_t*>(&r1);
    }
    {
        uint32_t sel = (c1.x & 7) | ((c1.y & 7) << 4) | ((c1.z & 7) << 8) |
                       ((c1.w & 7) << 12);
        uint32_t hb = __byte_perm(0x3E3C3800u, 0x46444240u, sel);
        uint32_t p0 = __byte_perm(hb, 0, 0x1404) |
                      ((c1.x & 8) << 12) | ((c1.y & 8) << 28);
        uint32_t p1 = __byte_perm(hb, 0, 0x3424) |
                      ((c1.z & 8) << 12) | ((c1.w & 8) << 28);
        __half2 r0 = __hmul2(*reinterpret_cast<__half2*>(&p0), hs2);
        __half2 r1 = __hmul2(*reinterpret_cast<__half2*>(&p1), hs2);
        o.z = *reinterpret_cast<uint32_t*>(&r0);
        o.w = *reinterpret_cast<uint32_t*>(&r1);
    }
    *reinterpret_cast<uint4*>(out + base) = o;
}

// ---- aux kernel: dequant W1 + convert x (W2 dequant moved into gemm0) ----
#define DQ_BLOCKS ((DDIM * (size_t)DDIM / 8) / 256)   // 8192
#define SP_BLOCKS ((TDIM * (size_t)DDIM / 8) / 256)   // 16384
__global__ void aux_kernel(const int* __restrict__ w1c, const float* __restrict__ w1s,
                           const float* __restrict__ x) {
    const size_t b = blockIdx.x;
    if (b < DQ_BLOCKS) {
        dequant8(w1c, w1s, g_w1, (b * 256 + threadIdx.x) * 8);
    } else {
        size_t base = ((b - DQ_BLOCKS) * 256 + threadIdx.x) * 8;
        float4 v0 = *reinterpret_cast<const float4*>(x + base);
        float4 v1 = *reinterpret_cast<const float4*>(x + base + 4);
        uint4 o;
        __half2 h;
        h = __floats2half2_rn(v0.x, v0.y); o.x = *reinterpret_cast<uint32_t*>(&h);
        h = __floats2half2_rn(v0.z, v0.w); o.y = *reinterpret_cast<uint32_t*>(&h);
        h = __floats2half2_rn(v1.x, v1.y); o.z = *reinterpret_cast<uint32_t*>(&h);
        h = __floats2half2_rn(v1.z, v1.w); o.w = *reinterpret_cast<uint32_t*>(&h);
        *reinterpret_cast<uint4*>(g_a + base) = o;
    }
}

__device__ __forceinline__ void ldmat4(uint32_t addr, uint32_t& d0, uint32_t& d1,
                                       uint32_t& d2, uint32_t& d3) {
    asm volatile("ldmatrix.sync.aligned.m8n8.x4.shared.b16 {%0,%1,%2,%3}, [%4];\n"
                 : "=r"(d0), "=r"(d1), "=r"(d2), "=r"(d3) : "r"(addr));
}

__device__ __forceinline__ void mma16816(float* c, const uint32_t* a, const uint32_t* b) {
    asm volatile(
        "mma.sync.aligned.m16n8k16.row.col.f32.f16.f16.f32 "
        "{%0,%1,%2,%3}, {%4,%5,%6,%7}, {%8,%9}, {%0,%1,%2,%3};\n"
        : "+f"(c[0]), "+f"(c[1]), "+f"(c[2]), "+f"(c[3])
        : "r"(a[0]), "r"(a[1]), "r"(a[2]), "r"(a[3]), "r"(b[0]), "r"(b[1]));
}

__device__ __forceinline__ void cp16(uint32_t saddr, const void* gaddr) {
    asm volatile("cp.async.cg.shared.global [%0], [%1], 16;\n"
                 :: "r"(saddr), "l"(gaddr));
}

// ====== GEMM: 128(M) x 128(N) CTA, 128 threads, 2 CTAs/SM, BK=64, 3 stages =
// 4 warps = 2(M) x 2(N), 64x64 per warp. Rotating stage offsets (no %).
// smem rows: 128B, chunk ^= (row & 7): conflict-free ldmatrix + writes.
// LAYER 0 additionally dequants its 8192-element slice of W2 during the
// prologue (overlaps DRAM-bound work under tensor-bound gemm0).
#define BK 64
#define STAGES 3
#define NCH (DDIM / BK)
#define W_BYTES (128 * BK * 2)
#define A_BYTES (128 * BK * 2)
#define STAGE_BYTES (W_BYTES + A_BYTES)
#define SMEM_BYTES (STAGES * STAGE_BYTES)

template <int LAYER>
__global__ void __launch_bounds__(128, 2)
gemm_kernel(const float* __restrict__ bias, float* __restrict__ outf,
            const int* __restrict__ w2c, const float* __restrict__ w2s) {
    extern __shared__ char dsm[];
    const __half* __restrict__ A = (LAYER == 0) ? g_a : g_h;
    const __half* __restrict__ W = (LAYER == 0) ? g_w1 : g_w2;

    __shared__ float sBias[128];

    const int tid = threadIdx.x;
    const int lane = tid & 31;
    const int wid = tid >> 5;
    const int wm = wid & 1;
    const int wn = wid >> 1;
    const int o0 = blockIdx.x * 128;
    const int t0 = blockIdx.y * 128;

    sBias[tid] = __ldg(bias + o0 + tid);

    const uint32_t sdyn = (uint32_t)__cvta_generic_to_shared(dsm);

    // ---- coalesced loader maps: 8 threads cover one row's 128B ----
    const int lc = tid & 7;
    const int lr = tid >> 3;
    const __half* pW = W + (size_t)(o0 + lr) * DDIM + lc * 8;
    const __half* pA = A + (size_t)(t0 + lr) * DDIM + lc * 8;
    uint32_t st[8];
#pragma unroll
    for (int s = 0; s < 8; s++) {
        int row = lr + 16 * s;
        st[s] = (uint32_t)(row * 128 + ((lc ^ (row & 7)) << 4));
    }

    // ---- mma fragment address components ----
    const int aRow = lane & 15;
    const int aKC = lane >> 4;
    const int bRow = (lane & 7) + ((lane >> 4) << 3);
    const int bKC = (lane >> 3) & 1;
    uint32_t aOff[4];
    int aXor[4];
#pragma unroll
    for (int mf = 0; mf < 4; mf++) {
        int row = wm * 64 + mf * 16 + aRow;
        aOff[mf] = (uint32_t)(row * 128);
        aXor[mf] = row & 7;
    }
    uint32_t bOff[4];
    int bXor[4];
#pragma unroll
    for (int nb = 0; nb < 4; nb++) {
        int row = wn * 64 + nb * 16 + bRow;
        bOff[nb] = (uint32_t)(row * 128);
        bXor[nb] = row & 7;
    }

    float acc[4][8][4];
#pragma unroll
    for (int i = 0; i < 4; i++)
#pragma unroll
        for (int j = 0; j < 8; j++)
#pragma unroll
            for (int k = 0; k < 4; k++) acc[i][j][k] = 0.f;

    // double-buffered fragments
    uint32_t af[2][4][4], bf[2][8][2];

    auto ldB = [&](int buf, uint32_t wb, int nb, int kc) {
        uint32_t addr = wb + bOff[nb] + (uint32_t)(((kc + bKC) ^ bXor[nb]) << 4);
        ldmat4(addr, bf[buf][nb * 2][0], bf[buf][nb * 2][1], bf[buf][nb * 2 + 1][0],
               bf[buf][nb * 2 + 1][1]);
    };
    auto ldA = [&](int buf, uint32_t ab, int mf, int kc) {
        uint32_t addr = ab + aOff[mf] + (uint32_t)(((kc + aKC) ^ aXor[mf]) << 4);
        ldmat4(addr, af[buf][mf][0], af[buf][mf][1], af[buf][mf][2], af[buf][mf][3]);
    };
    auto mma8 = [&](int mf, int buf) {
#pragma unroll
        for (int nf = 0; nf < 8; nf++) mma16816(acc[mf][nf], af[buf][mf], bf[buf][nf]);
    };

    // full-stage loader (prologue only)
    auto load_stage = [&](uint32_t wb, int k0) {
        const uint32_t ab = wb + W_BYTES;
#pragma unroll
        for (int q = 0; q < 8; q++)
            cp16(wb + st[q], pW + k0 + (size_t)q * 16 * DDIM);
#pragma unroll
        for (int q = 0; q < 8; q++)
            cp16(ab + st[q], pA + k0 + (size_t)q * 16 * DDIM);
        asm volatile("cp.async.commit_group;\n" ::: "memory");
    };

    // prologue: chunks 0,1 in flight
    load_stage(sdyn, 0);
    load_stage(sdyn + STAGE_BYTES, BK);

    // LAYER 0: dequant this CTA's slice of W2 while prologue tiles are in
    // flight (DRAM-bound work under tensor-bound gemm0; gemm1 consumes it
    // after the kernel boundary).
    if (LAYER == 0) {
        const size_t slice = ((size_t)blockIdx.y * (DDIM / 128) + blockIdx.x) * 8192;
#pragma unroll
        for (int k = 0; k < 8; k++)
            dequant8(w2c, w2s, g_w2, slice + (size_t)k * 1024 + tid * 8);
    }

    asm volatile("cp.async.wait_group 1;\n" ::: "memory");
    __syncthreads();
#pragma unroll
    for (int nb = 0; nb < 4; nb++) ldB(0, sdyn, nb, 0);
#pragma unroll
    for (int mf = 0; mf < 4; mf++) ldA(0, sdyn + W_BYTES, mf, 0);

    // rotating stage bases: wb = compute, wbn = next (visible), wbL = load dst
    uint32_t wb = sdyn;
    uint32_t wbn = sdyn + STAGE_BYTES;
    uint32_t wbL = sdyn + 2 * STAGE_BYTES;
    const __half* pWL = pW + 2 * BK;
    const __half* pAL = pA + 2 * BK;

#pragma unroll 1
    for (int i = 0; i < NCH; i++) {
        const uint32_t ab = wb + W_BYTES;
        const uint32_t abn = wbn + W_BYTES;
        const uint32_t abL = wbL + W_BYTES;
        const bool haveNext = (i + 1 < NCH);
        const bool load2 = (i + 2 < NCH);

        // ---- ksteps 0..2: next-kstep frags + 16 cp.async spread under MMA ----
#pragma unroll
        for (int j = 0; j < 3; j++) {
            const int cur = j & 1;
            const int nxt = cur ^ 1;
            const int kcN = 2 * (j + 1);
            ldB(nxt, wb, 0, kcN);
            ldB(nxt, wb, 1, kcN);
            mma8(0, cur);
            if (load2) {
                if (j == 0) {
                    cp16(wbL + st[0], pWL);
                    cp16(wbL + st[1], pWL + (size_t)16 * DDIM);
                    cp16(wbL + st[2], pWL + (size_t)32 * DDIM);
                } else if (j == 1) {
                    cp16(wbL + st[6], pWL + (size_t)96 * DDIM);
                    cp16(wbL + st[7], pWL + (size_t)112 * DDIM);
                    cp16(abL + st[0], pAL);
                } else {
                    cp16(abL + st[4], pAL + (size_t)64 * DDIM);
                    cp16(abL + st[5], pAL + (size_t)80 * DDIM);
                }
            }
            ldB(nxt, wb, 2, kcN);
            ldB(nxt, wb, 3, kcN);
            mma8(1, cur);
            if (load2) {
                if (j == 0) {
                    cp16(wbL + st[3], pWL + (size_t)48 * DDIM);
                    cp16(wbL + st[4], pWL + (size_t)64 * DDIM);
                    cp16(wbL + st[5], pWL + (size_t)80 * DDIM);
                } else if (j == 1) {
                    cp16(abL + st[1], pAL + (size_t)16 * DDIM);
                    cp16(abL + st[2], pAL + (size_t)32 * DDIM);
                    cp16(abL + st[3], pAL + (size_t)48 * DDIM);
                } else {
                    cp16(abL + st[6], pAL + (size_t)96 * DDIM);
                    cp16(abL + st[7], pAL + (size_t)112 * DDIM);
                }
            }
            ldA(nxt, ab, 0, kcN);
            ldA(nxt, ab, 1, kcN);
            mma8(2, cur);
            ldA(nxt, ab, 2, kcN);
            ldA(nxt, ab, 3, kcN);
            mma8(3, cur);
            if (j == 2 && load2)
                asm volatile("cp.async.commit_group;\n" ::: "memory");
        }

        // ---- kstep 3 (frags in buf1): barrier mid-burst, preload next chunk ----
        mma8(0, 1);
        mma8(1, 1);
        if (load2)
            asm volatile("cp.async.wait_group 1;\n" ::: "memory");
        else
            asm volatile("cp.async.wait_group 0;\n" ::: "memory");
        __syncthreads();
        if (haveNext) {
            ldB(0, wbn, 0, 0);
            ldB(0, wbn, 1, 0);
        }
        mma8(2, 1);
        if (haveNext) {
            ldB(0, wbn, 2, 0);
            ldB(0, wbn, 3, 0);
            ldA(0, abn, 0, 0);
            ldA(0, abn, 1, 0);
        }
        mma8(3, 1);
        if (haveNext) {
            ldA(0, abn, 2, 0);
            ldA(0, abn, 3, 0);
        }

        // rotate stages, advance load pointers
        uint32_t tmp = wb;
        wb = wbn;
        wbn = wbL;
        wbL = tmp;
        pWL += BK;
        pAL += BK;
    }

    // ---- epilogue ----
    const int gr = lane >> 2;
    const int tc2 = (lane & 3) * 2;
#pragma unroll
    for (int mf = 0; mf < 4; mf++) {
        const int row = t0 + wm * 64 + mf * 16 + gr;
#pragma unroll
        for (int nf = 0; nf < 8; nf++) {
            const int colL = wn * 64 + nf * 8 + tc2;
            const int col = o0 + colL;
            float bv0 = sBias[colL];
            float bv1 = sBias[colL + 1];
            float v00 = acc[mf][nf][0] + bv0;
            float v01 = acc[mf][nf][1] + bv1;
            float v10 = acc[mf][nf][2] + bv0;
            float v11 = acc[mf][nf][3] + bv1;
            if (LAYER == 0) {
                *reinterpret_cast<__half2*>(g_h + (size_t)row * DDIM + col) =
                    __floats2half2_rn(v00, v01);
                *reinterpret_cast<__half2*>(g_h + (size_t)(row + 8) * DDIM + col) =
                    __floats2half2_rn(v10, v11);
            } else {
                *reinterpret_cast<float2*>(outf + (size_t)row * DDIM + col) =
                    make_float2(v00, v01);
                *reinterpret_cast<float2*>(outf + (size_t)(row + 8) * DDIM + col) =
                    make_float2(v10, v11);
            }
        }
    }
}

extern "C" void kernel_launch(void* const* d_in, const int* in_sizes, int n_in,
                              void* d_out, int out_size) {
    const float* x = (const float*)d_in[0];
    const int* w1c = (const int*)d_in[1];
    const float* w1s = (const float*)d_in[2];
    const float* b1 = (const float*)d_in[3];
    const int* w2c = (const int*)d_in[4];
    const float* w2s = (const float*)d_in[5];
    const float* b2 = (const float*)d_in[6];
    float* out = (float*)d_out;

    cudaFuncSetAttribute(gemm_kernel<0>, cudaFuncAttributeMaxDynamicSharedMemorySize,
                         SMEM_BYTES);
    cudaFuncSetAttribute(gemm_kernel<1>, cudaFuncAttributeMaxDynamicSharedMemorySize,
                         SMEM_BYTES);

    aux_kernel<<<(unsigned)(DQ_BLOCKS + SP_BLOCKS), 256>>>(w1c, w1s, x);

    dim3 grid(DDIM / 128, TDIM / 128);
    gemm_kernel<0><<<grid, 128, SMEM_BYTES>>>(b1, nullptr, w2c, w2s);
    gemm_kernel<1><<<grid, 128, SMEM_BYTES>>>(b2, out, nullptr, nullptr);
}